// round 8
// baseline (speedup 1.0000x reference)
#include <cuda_runtime.h>
#include <cstdint>

#define VOCAB 400000
#define DIM 300
#define KP 320                 // padded K in elements (zeros 300..319)
#define NQ 512
#define TOPK 5
#define CAND 16
#define BN 64                  // vocab rows per tile
#define NTILES (VOCAB / BN)    // 6250
#define GRIDX 148
#define QGROUP 128
#define NQG (NQ / QGROUP)      // 4

#define PITCH 336              // smem row pitch bytes (21*16B, conflict-free ldmatrix)
#define ABYTES (QGROUP * PITCH)        // 43008
#define BBYTES (BN * PITCH)            // 21504
#define DPITCH 66
#define DBYTES (QGROUP * DPITCH * 4)   // 33792
#define SVBYTES (BN * 4)
#define SMEM_BYTES (1024 + ABYTES + 2 * BBYTES + DBYTES + SVBYTES)

// ---------------- device scratch (no allocation allowed) -------------------
__device__ float g_invnorm[VOCAB];
__device__ float g_scale[VOCAB];                       // maxabs*inv/127
__device__ __align__(128) signed char g_E8[(size_t)VOCAB * KP];   // 128 MB
__device__ __align__(128) signed char g_Q8[NQ * KP];
__device__ float g_cv[(size_t)NQ * GRIDX * CAND];
__device__ int   g_ci[(size_t)NQ * GRIDX * CAND];

// ---------------- PTX helpers ----------------------------------------------
__device__ __forceinline__ uint32_t smem_u32(const void* p) {
    uint32_t a;
    asm("{ .reg .u64 t; cvta.to.shared.u64 t, %1; cvt.u32.u64 %0, t; }" : "=r"(a) : "l"(p));
    return a;
}
__device__ __forceinline__ void cpa16(uint32_t dst, const void* src) {
    asm volatile("cp.async.cg.shared.global [%0], [%1], 16;" :: "r"(dst), "l"(src) : "memory");
}
#define CP_COMMIT() asm volatile("cp.async.commit_group;" ::: "memory")
#define CP_WAIT(n)  asm volatile("cp.async.wait_group %0;" :: "n"(n) : "memory")

__device__ __forceinline__ void ldsm_x4(uint32_t* r, uint32_t addr) {
    asm volatile("ldmatrix.sync.aligned.m8n8.x4.shared.b16 {%0,%1,%2,%3}, [%4];"
                 : "=r"(r[0]), "=r"(r[1]), "=r"(r[2]), "=r"(r[3]) : "r"(addr));
}
// int8 MMA: D(s32) += A(s8) * B(s8), m16n8k32
__device__ __forceinline__ void mma_s8(int* d, const uint32_t* a, uint32_t b0, uint32_t b1) {
    asm volatile("mma.sync.aligned.m16n8k32.row.col.s32.s8.s8.s32 "
                 "{%0,%1,%2,%3}, {%4,%5,%6,%7}, {%8,%9}, {%0,%1,%2,%3};"
                 : "+r"(d[0]), "+r"(d[1]), "+r"(d[2]), "+r"(d[3])
                 : "r"(a[0]), "r"(a[1]), "r"(a[2]), "r"(a[3]), "r"(b0), "r"(b1));
}

// ---------------- ordering helpers -----------------------------------------
__device__ __forceinline__ bool better(float av, int an, float bv, int bn) {
    return (av > bv) || (av == bv && an < bn);
}
__device__ __forceinline__ void ins16(float s, int n, float* v, int* nn) {
    if (better(s, n, v[CAND - 1], nn[CAND - 1])) {
        v[CAND - 1] = s; nn[CAND - 1] = n;
        #pragma unroll
        for (int j = CAND - 1; j > 0; j--) {
            if (better(v[j], nn[j], v[j - 1], nn[j - 1])) {
                float tv = v[j]; v[j] = v[j - 1]; v[j - 1] = tv;
                int tn = nn[j]; nn[j] = nn[j - 1]; nn[j - 1] = tn;
            }
        }
    }
}
__device__ __forceinline__ void merge16(float* v, int* nn, const float* ov, const int* on) {
    float rv[CAND]; int rn[CAND]; int a = 0, b = 0;
    #pragma unroll
    for (int j = 0; j < CAND; j++) {
        bool ta = better(v[a], nn[a], ov[b], on[b]);
        rv[j] = ta ? v[a] : ov[b];
        rn[j] = ta ? nn[a] : on[b];
        if (ta) a++; else b++;
    }
    #pragma unroll
    for (int j = 0; j < CAND; j++) { v[j] = rv[j]; nn[j] = rn[j]; }
}

// ---------------------------------------------------------------------------
// Kernel 1: per-row invnorm + maxabs -> int8 quantized table + scale
//           int8 = round(x * 127 / maxabs_raw);  scale = maxabs_raw*inv/127
// ---------------------------------------------------------------------------
__global__ void prep_kernel(const float* __restrict__ E) {
    int row = blockIdx.x * (blockDim.x >> 5) + (threadIdx.x >> 5);
    int lane = threadIdx.x & 31;
    if (row >= VOCAB) return;
    const float4* r4 = (const float4*)(E + (size_t)row * DIM);
    float s = 0.f, mx = 0.f;
    for (int i = lane; i < DIM / 4; i += 32) {
        float4 v = r4[i];
        s += v.x * v.x + v.y * v.y + v.z * v.z + v.w * v.w;
        mx = fmaxf(mx, fmaxf(fmaxf(fabsf(v.x), fabsf(v.y)), fmaxf(fabsf(v.z), fabsf(v.w))));
    }
    #pragma unroll
    for (int off = 16; off; off >>= 1) {
        s += __shfl_xor_sync(0xffffffffu, s, off);
        mx = fmaxf(mx, __shfl_xor_sync(0xffffffffu, mx, off));
    }
    float inv = 1.0f / sqrtf(s);
    float qs = 127.0f / mx;
    if (lane == 0) { g_invnorm[row] = inv; g_scale[row] = mx * inv * (1.0f / 127.0f); }
    const float* src = E + (size_t)row * DIM;
    int* dst = (int*)(g_E8 + (size_t)row * KP);
    for (int j = lane; j < KP / 4; j += 32) {
        int k = 4 * j;
        int b0 = (k     < DIM) ? __float2int_rn(src[k]     * qs) : 0;
        int b1 = (k + 1 < DIM) ? __float2int_rn(src[k + 1] * qs) : 0;
        int b2 = (k + 2 < DIM) ? __float2int_rn(src[k + 2] * qs) : 0;
        int b3 = (k + 3 < DIM) ? __float2int_rn(src[k + 3] * qs) : 0;
        dst[j] = (b0 & 0xff) | ((b1 & 0xff) << 8) | ((b2 & 0xff) << 16) | ((b3 & 0xff) << 24);
    }
}

// ---------------------------------------------------------------------------
// Kernel 2: gather queries -> int8 (query scale is uniform per query: ignored)
// ---------------------------------------------------------------------------
__global__ void gatherq_kernel(const float* __restrict__ E, const int* __restrict__ ids) {
    int q = blockIdx.x * (blockDim.x >> 5) + (threadIdx.x >> 5);
    int lane = threadIdx.x & 31;
    if (q >= NQ) return;
    int id = ids[q];
    const float* src = E + (size_t)id * DIM;
    float mx = 0.f;
    for (int k = lane; k < DIM; k += 32) mx = fmaxf(mx, fabsf(src[k]));
    #pragma unroll
    for (int off = 16; off; off >>= 1) mx = fmaxf(mx, __shfl_xor_sync(0xffffffffu, mx, off));
    float qs = 127.0f / mx;
    int* dst = (int*)(g_Q8 + (size_t)q * KP);
    for (int j = lane; j < KP / 4; j += 32) {
        int k = 4 * j;
        int b0 = (k     < DIM) ? __float2int_rn(src[k]     * qs) : 0;
        int b1 = (k + 1 < DIM) ? __float2int_rn(src[k + 1] * qs) : 0;
        int b2 = (k + 2 < DIM) ? __float2int_rn(src[k + 2] * qs) : 0;
        int b3 = (k + 3 < DIM) ? __float2int_rn(src[k + 3] * qs) : 0;
        dst[j] = (b0 & 0xff) | ((b1 & 0xff) << 8) | ((b2 & 0xff) << 16) | ((b3 & 0xff) << 24);
    }
}

// ---------------------------------------------------------------------------
// Kernel 3: int8 mma.sync GEMM (128 queries x 64 vocab x K=320) + top-16
// 256 threads = 8 warps (4 in M x 2 in N). Warp tile 32x32. 10 k-steps.
// ---------------------------------------------------------------------------
__global__ __launch_bounds__(256, 1) void gemm_topk_kernel() {
    extern __shared__ char smem[];
    uint32_t sb = smem_u32(smem);
    uint32_t ab = (sb + 1023u) & ~1023u;
    const uint32_t A_S = ab;
    const uint32_t B_S = ab + ABYTES;
    int*   Ds  = (int*)(smem + (ab - sb) + ABYTES + 2 * BBYTES);
    float* svs = (float*)(smem + (ab - sb) + ABYTES + 2 * BBYTES + DBYTES);

    const int tid = threadIdx.x;
    const int lane = tid & 31;
    const int wid = tid >> 5;
    const int wm = wid & 3;          // 0..3 -> M (32-row slices)
    const int wn = wid >> 2;         // 0..1 -> N (32-col slices)
    const int qg = blockIdx.x;
    const int bx = blockIdx.y;
    const int nt = (NTILES - bx + GRIDX - 1) / GRIDX;

    // A load (resident) + first B tile. 20 x 16B chunks per 320B row.
    const signed char* Qsrc = g_Q8 + (size_t)qg * QGROUP * KP;
    for (int i = tid; i < QGROUP * 20; i += 256)
        cpa16(A_S + (i / 20) * PITCH + (i % 20) * 16, Qsrc + (size_t)(i / 20) * KP + (i % 20) * 16);
    {
        const signed char* src = g_E8 + (size_t)bx * BN * KP;
        for (int i = tid; i < BN * 20; i += 256)
            cpa16(B_S + (i / 20) * PITCH + (i % 20) * 16, src + (size_t)(i / 20) * KP + (i % 20) * 16);
    }
    CP_COMMIT();

    // ldmatrix address lanes (add k0 bytes per k-step):
    // groups: 0-7 rows0-7 chunk0 | 8-15 rows8-15 chunk0 | 16-23 rows0-7 chunk1 | 24-31 rows8-15 chunk1
    uint32_t a_off[2], b_off[2];
    {
        int rr = (lane & 7) + ((lane >> 3) & 1) * 8;
        int ck = (lane >> 4) * 16;
        #pragma unroll
        for (int mt = 0; mt < 2; mt++)
            a_off[mt] = A_S + (uint32_t)(wm * 32 + mt * 16 + rr) * PITCH + ck;
        #pragma unroll
        for (int np = 0; np < 2; np++)
            b_off[np] = (uint32_t)(wn * 32 + np * 16 + rr) * PITCH + ck;
    }

    float cv[CAND]; int ci[CAND];
    #pragma unroll
    for (int j = 0; j < CAND; j++) { cv[j] = -1e30f; ci[j] = 0x7fffffff; }

    for (int t = 0; t < nt; t++) {
        if (t + 1 < nt) {
            int vt = bx + (t + 1) * GRIDX;
            uint32_t base = B_S + (uint32_t)((t + 1) & 1) * BBYTES;
            const signed char* src = g_E8 + (size_t)vt * BN * KP;
            for (int i = tid; i < BN * 20; i += 256)
                cpa16(base + (i / 20) * PITCH + (i % 20) * 16, src + (size_t)(i / 20) * KP + (i % 20) * 16);
            CP_COMMIT();
            CP_WAIT(1);
        } else {
            CP_WAIT(0);
        }
        // stage per-row scales for this tile
        if (tid < BN) svs[tid] = g_scale[(bx + t * GRIDX) * BN + tid];
        __syncthreads();

        uint32_t Bbase = B_S + (uint32_t)(t & 1) * BBYTES;
        int d[2][4][4];
        #pragma unroll
        for (int mt = 0; mt < 2; mt++)
            #pragma unroll
            for (int n = 0; n < 4; n++)
                #pragma unroll
                for (int j = 0; j < 4; j++) d[mt][n][j] = 0;

        #pragma unroll
        for (int k0 = 0; k0 < KP; k0 += 32) {
            uint32_t a[2][4], b[2][4];
            ldsm_x4(a[0], a_off[0] + k0);
            ldsm_x4(a[1], a_off[1] + k0);
            ldsm_x4(b[0], Bbase + b_off[0] + k0);
            ldsm_x4(b[1], Bbase + b_off[1] + k0);
            #pragma unroll
            for (int mt = 0; mt < 2; mt++) {
                mma_s8(d[mt][0], a[mt], b[0][0], b[0][2]);   // cols 0-7
                mma_s8(d[mt][1], a[mt], b[0][1], b[0][3]);   // cols 8-15
                mma_s8(d[mt][2], a[mt], b[1][0], b[1][2]);   // cols 16-23
                mma_s8(d[mt][3], a[mt], b[1][1], b[1][3]);   // cols 24-31
            }
        }

        // stage D (s32) to smem
        #pragma unroll
        for (int mt = 0; mt < 2; mt++) {
            int r0 = wm * 32 + mt * 16 + (lane >> 2);
            #pragma unroll
            for (int n = 0; n < 4; n++) {
                int c0 = wn * 32 + n * 8 + (lane & 3) * 2;
                *(int2*)&Ds[r0 * DPITCH + c0]       = make_int2(d[mt][n][0], d[mt][n][1]);
                *(int2*)&Ds[(r0 + 8) * DPITCH + c0] = make_int2(d[mt][n][2], d[mt][n][3]);
            }
        }
        __syncthreads();

        // per-query top-16 scan (1 thread per query row), scale by per-vocab-row s_v
        if (tid < QGROUP) {
            const int* row = Ds + tid * DPITCH;
            int vbase = (bx + t * GRIDX) * BN;
            #pragma unroll 8
            for (int c = 0; c < BN; c++)
                ins16((float)row[c] * svs[c], vbase + c, cv, ci);
        }
        __syncthreads();
    }

    if (tid < QGROUP) {
        int q = qg * QGROUP + tid;
        size_t base = ((size_t)q * GRIDX + bx) * CAND;
        #pragma unroll
        for (int j = 0; j < CAND; j++) { g_cv[base + j] = cv[j]; g_ci[base + j] = ci[j]; }
    }
}

// ---------------------------------------------------------------------------
// Kernel 4: global approx top-16 -> exact fp32 rescore -> top-5 out
// ---------------------------------------------------------------------------
__global__ void final_kernel(const float* __restrict__ E, const int* __restrict__ ids,
                             float* __restrict__ out) {
    __shared__ float sv[256][CAND];
    __shared__ int   sn[256][CAND];
    __shared__ float ev[CAND];
    int q = blockIdx.x, tid = threadIdx.x;

    float v[CAND]; int nn[CAND];
    #pragma unroll
    for (int j = 0; j < CAND; j++) { v[j] = -1e30f; nn[j] = 0x7fffffff; }
    size_t base = (size_t)q * GRIDX * CAND;
    for (int i = tid; i < GRIDX * CAND; i += 256) ins16(g_cv[base + i], g_ci[base + i], v, nn);
    #pragma unroll
    for (int j = 0; j < CAND; j++) { sv[tid][j] = v[j]; sn[tid][j] = nn[j]; }
    __syncthreads();
    for (int s = 128; s > 0; s >>= 1) {
        if (tid < s) {
            float ov[CAND]; int on[CAND];
            #pragma unroll
            for (int j = 0; j < CAND; j++) {
                v[j] = sv[tid][j]; nn[j] = sn[tid][j];
                ov[j] = sv[tid + s][j]; on[j] = sn[tid + s][j];
            }
            merge16(v, nn, ov, on);
            #pragma unroll
            for (int j = 0; j < CAND; j++) { sv[tid][j] = v[j]; sn[tid][j] = nn[j]; }
        }
        __syncthreads();
    }
    // exact fp32 rescore of the 16 surviving candidates
    int wid = tid >> 5, lane = tid & 31;
    int qid = ids[q];
    float invq = g_invnorm[qid];
    for (int c = wid; c < CAND; c += 8) {
        int vi = sn[0][c];
        float val = -1e30f;
        if (vi >= 0 && vi < VOCAB) {
            const float* a = E + (size_t)qid * DIM;
            const float* b = E + (size_t)vi * DIM;
            float s = 0.f;
            for (int k = lane; k < DIM; k += 32) s += a[k] * b[k];
            #pragma unroll
            for (int off = 16; off; off >>= 1) s += __shfl_xor_sync(0xffffffffu, s, off);
            val = s * invq * g_invnorm[vi];
        }
        if (lane == 0) ev[c] = val;
    }
    __syncthreads();
    if (tid == 0) {
        bool used[CAND];
        #pragma unroll
        for (int j = 0; j < CAND; j++) used[j] = false;
        for (int j = 0; j < TOPK; j++) {
            int best = -1;
            for (int c = 0; c < CAND; c++) {
                if (used[c]) continue;
                if (best < 0 || better(ev[c], sn[0][c], ev[best], sn[0][best])) best = c;
            }
            used[best] = true;
            out[q * TOPK + j] = ev[best];
            out[NQ * TOPK + q * TOPK + j] = (float)sn[0][best];
        }
    }
}

// ---------------------------------------------------------------------------
extern "C" void kernel_launch(void* const* d_in, const int* in_sizes, int n_in,
                              void* d_out, int out_size) {
    const float* E = (const float*)d_in[0];
    const int* ids = (const int*)d_in[1];
    float* out = (float*)d_out;

    cudaFuncSetAttribute(gemm_topk_kernel, cudaFuncAttributeMaxDynamicSharedMemorySize, SMEM_BYTES);

    prep_kernel<<<VOCAB / 8, 256>>>(E);
    gatherq_kernel<<<NQ / 8, 256>>>(E, ids);
    gemm_topk_kernel<<<dim3(NQG, GRIDX), 256, SMEM_BYTES>>>();
    final_kernel<<<NQ, 256>>>(E, ids, out);
}

// round 10
// speedup vs baseline: 1.6653x; 1.6653x over previous
#include <cuda_runtime.h>
#include <cstdint>

#define VOCAB 400000
#define DIM 300
#define KP 320                 // padded K (zeros 300..319), 20 x 16B chunks
#define NCH (KP / 16)          // 20
#define NQ 512
#define TOPK 5
#define CAND 16
#define BN 64                  // vocab rows per tile
#define NTILES (VOCAB / BN)    // 6250
#define GRIDX 148
#define QGROUP 128
#define NQG (NQ / QGROUP)      // 4

#define PITCH 336              // smem row pitch bytes (21*16)
#define ABYTES (QGROUP * PITCH)        // 43008
#define BBYTES (BN * PITCH)            // 21504
#define DPITCH 65              // floats (odd -> conflict-free row scan)
#define DBYTES (QGROUP * DPITCH * 4)   // 33280
#define SVBYTES (BN * 4)
#define SMEM_BYTES (1024 + ABYTES + 2 * BBYTES + DBYTES + SVBYTES)

// ---------------- device scratch (no allocation allowed) -------------------
__device__ float g_invnorm[VOCAB];
__device__ float g_scale[VOCAB];                       // maxabs*inv/127
__device__ __align__(128) signed char g_E8[(size_t)VOCAB * KP];   // 128 MB
__device__ __align__(128) signed char g_Q8[NQ * KP];
__device__ float g_cv[(size_t)NQ * GRIDX * CAND];
__device__ int   g_ci[(size_t)NQ * GRIDX * CAND];

// ---------------- PTX helpers ----------------------------------------------
__device__ __forceinline__ uint32_t smem_u32(const void* p) {
    uint32_t a;
    asm("{ .reg .u64 t; cvta.to.shared.u64 t, %1; cvt.u32.u64 %0, t; }" : "=r"(a) : "l"(p));
    return a;
}
__device__ __forceinline__ void cpa16(uint32_t dst, const void* src) {
    asm volatile("cp.async.cg.shared.global [%0], [%1], 16;" :: "r"(dst), "l"(src) : "memory");
}
#define CP_COMMIT() asm volatile("cp.async.commit_group;" ::: "memory")
#define CP_WAIT(n)  asm volatile("cp.async.wait_group %0;" :: "n"(n) : "memory")

__device__ __forceinline__ int4 lds128(uint32_t addr) {
    int4 v;
    asm volatile("ld.shared.v4.b32 {%0,%1,%2,%3}, [%4];"
                 : "=r"(v.x), "=r"(v.y), "=r"(v.z), "=r"(v.w) : "r"(addr));
    return v;
}

// ---------------- ordering helpers -----------------------------------------
__device__ __forceinline__ bool better(float av, int an, float bv, int bn) {
    return (av > bv) || (av == bv && an < bn);
}
__device__ __forceinline__ void ins16(float s, int n, float* v, int* nn) {
    if (better(s, n, v[CAND - 1], nn[CAND - 1])) {
        v[CAND - 1] = s; nn[CAND - 1] = n;
        #pragma unroll
        for (int j = CAND - 1; j > 0; j--) {
            if (better(v[j], nn[j], v[j - 1], nn[j - 1])) {
                float tv = v[j]; v[j] = v[j - 1]; v[j - 1] = tv;
                int tn = nn[j]; nn[j] = nn[j - 1]; nn[j - 1] = tn;
            }
        }
    }
}
__device__ __forceinline__ void merge16(float* v, int* nn, const float* ov, const int* on) {
    float rv[CAND]; int rn[CAND]; int a = 0, b = 0;
    #pragma unroll
    for (int j = 0; j < CAND; j++) {
        bool ta = better(v[a], nn[a], ov[b], on[b]);
        rv[j] = ta ? v[a] : ov[b];
        rn[j] = ta ? nn[a] : on[b];
        if (ta) a++; else b++;
    }
    #pragma unroll
    for (int j = 0; j < CAND; j++) { v[j] = rv[j]; nn[j] = rn[j]; }
}

// ---------------------------------------------------------------------------
// Kernel 1: per-row invnorm + maxabs -> int8 quantized table + scale
// ---------------------------------------------------------------------------
__global__ void prep_kernel(const float* __restrict__ E) {
    int row = blockIdx.x * (blockDim.x >> 5) + (threadIdx.x >> 5);
    int lane = threadIdx.x & 31;
    if (row >= VOCAB) return;
    const float4* r4 = (const float4*)(E + (size_t)row * DIM);
    float s = 0.f, mx = 0.f;
    for (int i = lane; i < DIM / 4; i += 32) {
        float4 v = r4[i];
        s += v.x * v.x + v.y * v.y + v.z * v.z + v.w * v.w;
        mx = fmaxf(mx, fmaxf(fmaxf(fabsf(v.x), fabsf(v.y)), fmaxf(fabsf(v.z), fabsf(v.w))));
    }
    #pragma unroll
    for (int off = 16; off; off >>= 1) {
        s += __shfl_xor_sync(0xffffffffu, s, off);
        mx = fmaxf(mx, __shfl_xor_sync(0xffffffffu, mx, off));
    }
    float inv = 1.0f / sqrtf(s);
    float qs = 127.0f / mx;
    if (lane == 0) { g_invnorm[row] = inv; g_scale[row] = mx * inv * (1.0f / 127.0f); }
    const float* src = E + (size_t)row * DIM;
    int* dst = (int*)(g_E8 + (size_t)row * KP);
    for (int j = lane; j < KP / 4; j += 32) {
        int k = 4 * j;
        int b0 = (k     < DIM) ? __float2int_rn(src[k]     * qs) : 0;
        int b1 = (k + 1 < DIM) ? __float2int_rn(src[k + 1] * qs) : 0;
        int b2 = (k + 2 < DIM) ? __float2int_rn(src[k + 2] * qs) : 0;
        int b3 = (k + 3 < DIM) ? __float2int_rn(src[k + 3] * qs) : 0;
        dst[j] = (b0 & 0xff) | ((b1 & 0xff) << 8) | ((b2 & 0xff) << 16) | ((b3 & 0xff) << 24);
    }
}

// ---------------------------------------------------------------------------
// Kernel 2: gather queries -> int8 (query-side scale uniform per query)
// ---------------------------------------------------------------------------
__global__ void gatherq_kernel(const float* __restrict__ E, const int* __restrict__ ids) {
    int q = blockIdx.x * (blockDim.x >> 5) + (threadIdx.x >> 5);
    int lane = threadIdx.x & 31;
    if (q >= NQ) return;
    int id = ids[q];
    const float* src = E + (size_t)id * DIM;
    float mx = 0.f;
    for (int k = lane; k < DIM; k += 32) mx = fmaxf(mx, fabsf(src[k]));
    #pragma unroll
    for (int off = 16; off; off >>= 1) mx = fmaxf(mx, __shfl_xor_sync(0xffffffffu, mx, off));
    float qs = 127.0f / mx;
    int* dst = (int*)(g_Q8 + (size_t)q * KP);
    for (int j = lane; j < KP / 4; j += 32) {
        int k = 4 * j;
        int b0 = (k     < DIM) ? __float2int_rn(src[k]     * qs) : 0;
        int b1 = (k + 1 < DIM) ? __float2int_rn(src[k + 1] * qs) : 0;
        int b2 = (k + 2 < DIM) ? __float2int_rn(src[k + 2] * qs) : 0;
        int b3 = (k + 3 < DIM) ? __float2int_rn(src[k + 3] * qs) : 0;
        dst[j] = (b0 & 0xff) | ((b1 & 0xff) << 8) | ((b2 & 0xff) << 16) | ((b3 & 0xff) << 24);
    }
}

// ---------------------------------------------------------------------------
// Kernel 3: dp4a GEMM (128 queries x 64 vocab x K=320) + per-query top-16
// 256 threads: tx = tid&15 (cols tx+16j), ty = tid>>4 (rows ty+16i)
// ---------------------------------------------------------------------------
__global__ __launch_bounds__(256, 1) void gemm_topk_kernel() {
    extern __shared__ char smem[];
    uint32_t sb = smem_u32(smem);
    uint32_t ab = (sb + 1023u) & ~1023u;
    const uint32_t A_S = ab;
    const uint32_t B_S = ab + ABYTES;
    float* Ds  = (float*)(smem + (ab - sb) + ABYTES + 2 * BBYTES);
    float* svs = (float*)(smem + (ab - sb) + ABYTES + 2 * BBYTES + DBYTES);

    const int tid = threadIdx.x;
    const int tx = tid & 15;
    const int ty = tid >> 4;
    const int qg = blockIdx.x;
    const int bx = blockIdx.y;
    const int nt = (NTILES - bx + GRIDX - 1) / GRIDX;

    // A load (resident) + first B tile
    const signed char* Qsrc = g_Q8 + (size_t)qg * QGROUP * KP;
    for (int i = tid; i < QGROUP * NCH; i += 256)
        cpa16(A_S + (i / NCH) * PITCH + (i % NCH) * 16, Qsrc + (size_t)(i / NCH) * KP + (i % NCH) * 16);
    {
        const signed char* src = g_E8 + (size_t)bx * BN * KP;
        for (int i = tid; i < BN * NCH; i += 256)
            cpa16(B_S + (i / NCH) * PITCH + (i % NCH) * 16, src + (size_t)(i / NCH) * KP + (i % NCH) * 16);
    }
    CP_COMMIT();

    float cv[CAND]; int ci[CAND];
    #pragma unroll
    for (int j = 0; j < CAND; j++) { cv[j] = -1e30f; ci[j] = 0x7fffffff; }

    for (int t = 0; t < nt; t++) {
        if (t + 1 < nt) {
            int vt = bx + (t + 1) * GRIDX;
            uint32_t base = B_S + (uint32_t)((t + 1) & 1) * BBYTES;
            const signed char* src = g_E8 + (size_t)vt * BN * KP;
            for (int i = tid; i < BN * NCH; i += 256)
                cpa16(base + (i / NCH) * PITCH + (i % NCH) * 16, src + (size_t)(i / NCH) * KP + (i % NCH) * 16);
            CP_COMMIT();
            CP_WAIT(1);
        } else {
            CP_WAIT(0);
        }
        if (tid < BN) svs[tid] = g_scale[(bx + t * GRIDX) * BN + tid];
        __syncthreads();

        const uint32_t Bb = B_S + (uint32_t)(t & 1) * BBYTES;
        int acc[8][4];
        #pragma unroll
        for (int i = 0; i < 8; i++)
            #pragma unroll
            for (int j = 0; j < 4; j++) acc[i][j] = 0;

        #pragma unroll 2
        for (int c = 0; c < NCH; c++) {
            int4 bf[4];
            #pragma unroll
            for (int j = 0; j < 4; j++)
                bf[j] = lds128(Bb + (uint32_t)(tx + 16 * j) * PITCH + c * 16);
            #pragma unroll
            for (int i = 0; i < 8; i++) {
                int4 af = lds128(A_S + (uint32_t)(ty + 16 * i) * PITCH + c * 16);
                #pragma unroll
                for (int j = 0; j < 4; j++) {
                    int s = acc[i][j];
                    s = __dp4a(af.x, bf[j].x, s);
                    s = __dp4a(af.y, bf[j].y, s);
                    s = __dp4a(af.z, bf[j].z, s);
                    s = __dp4a(af.w, bf[j].w, s);
                    acc[i][j] = s;
                }
            }
        }

        // stage scaled D to smem
        #pragma unroll
        for (int i = 0; i < 8; i++) {
            int r = ty + 16 * i;
            #pragma unroll
            for (int j = 0; j < 4; j++) {
                int cidx = tx + 16 * j;
                Ds[r * DPITCH + cidx] = (float)acc[i][j] * svs[cidx];
            }
        }
        __syncthreads();

        // per-query top-16 scan (1 thread per query row)
        if (tid < QGROUP) {
            const float* row = Ds + tid * DPITCH;
            int vbase = (bx + t * GRIDX) * BN;
            #pragma unroll 8
            for (int cc = 0; cc < BN; cc++) ins16(row[cc], vbase + cc, cv, ci);
        }
        __syncthreads();
    }

    if (tid < QGROUP) {
        int q = qg * QGROUP + tid;
        size_t base = ((size_t)q * GRIDX + bx) * CAND;
        #pragma unroll
        for (int j = 0; j < CAND; j++) { g_cv[base + j] = cv[j]; g_ci[base + j] = ci[j]; }
    }
}

// ---------------------------------------------------------------------------
// Kernel 4: global approx top-16 -> exact fp32 rescore -> top-5 out
// ---------------------------------------------------------------------------
__global__ void final_kernel(const float* __restrict__ E, const int* __restrict__ ids,
                             float* __restrict__ out) {
    __shared__ float sv[256][CAND];
    __shared__ int   sn[256][CAND];
    __shared__ float ev[CAND];
    int q = blockIdx.x, tid = threadIdx.x;

    float v[CAND]; int nn[CAND];
    #pragma unroll
    for (int j = 0; j < CAND; j++) { v[j] = -1e30f; nn[j] = 0x7fffffff; }
    size_t base = (size_t)q * GRIDX * CAND;
    for (int i = tid; i < GRIDX * CAND; i += 256) ins16(g_cv[base + i], g_ci[base + i], v, nn);
    #pragma unroll
    for (int j = 0; j < CAND; j++) { sv[tid][j] = v[j]; sn[tid][j] = nn[j]; }
    __syncthreads();
    for (int s = 128; s > 0; s >>= 1) {
        if (tid < s) {
            float ov[CAND]; int on[CAND];
            #pragma unroll
            for (int j = 0; j < CAND; j++) {
                v[j] = sv[tid][j]; nn[j] = sn[tid][j];
                ov[j] = sv[tid + s][j]; on[j] = sn[tid + s][j];
            }
            merge16(v, nn, ov, on);
            #pragma unroll
            for (int j = 0; j < CAND; j++) { sv[tid][j] = v[j]; sn[tid][j] = nn[j]; }
        }
        __syncthreads();
    }
    // exact fp32 rescore of the 16 surviving candidates
    int wid = tid >> 5, lane = tid & 31;
    int qid = ids[q];
    float invq = g_invnorm[qid];
    for (int c = wid; c < CAND; c += 8) {
        int vi = sn[0][c];
        float val = -1e30f;
        if (vi >= 0 && vi < VOCAB) {
            const float* a = E + (size_t)qid * DIM;
            const float* b = E + (size_t)vi * DIM;
            float s = 0.f;
            for (int k = lane; k < DIM; k += 32) s += a[k] * b[k];
            #pragma unroll
            for (int off = 16; off; off >>= 1) s += __shfl_xor_sync(0xffffffffu, s, off);
            val = s * invq * g_invnorm[vi];
        }
        if (lane == 0) ev[c] = val;
    }
    __syncthreads();
    if (tid == 0) {
        bool used[CAND];
        #pragma unroll
        for (int j = 0; j < CAND; j++) used[j] = false;
        for (int j = 0; j < TOPK; j++) {
            int best = -1;
            for (int c = 0; c < CAND; c++) {
                if (used[c]) continue;
                if (best < 0 || better(ev[c], sn[0][c], ev[best], sn[0][best])) best = c;
            }
            used[best] = true;
            out[q * TOPK + j] = ev[best];
            out[NQ * TOPK + q * TOPK + j] = (float)sn[0][best];
        }
    }
}

// ---------------------------------------------------------------------------
extern "C" void kernel_launch(void* const* d_in, const int* in_sizes, int n_in,
                              void* d_out, int out_size) {
    const float* E = (const float*)d_in[0];
    const int* ids = (const int*)d_in[1];
    float* out = (float*)d_out;

    cudaFuncSetAttribute(gemm_topk_kernel, cudaFuncAttributeMaxDynamicSharedMemorySize, SMEM_BYTES);

    prep_kernel<<<VOCAB / 8, 256>>>(E);
    gatherq_kernel<<<NQ / 8, 256>>>(E, ids);
    gemm_topk_kernel<<<dim3(NQG, GRIDX), 256, SMEM_BYTES>>>();
    final_kernel<<<NQ, 256>>>(E, ids, out);
}

// round 11
// speedup vs baseline: 1.7501x; 1.0509x over previous
#include <cuda_runtime.h>
#include <cstdint>

#define VOCAB 400000
#define DIM 300
#define KP 320                 // padded K (zeros 300..319), 20 x 16B chunks
#define NCH (KP / 16)          // 20
#define NQ 512
#define TOPK 5
#define CAND 16
#define BN 64                  // vocab rows per tile
#define NTILES (VOCAB / BN)    // 6250
#define GRIDX 148
#define QGROUP 64
#define NQG (NQ / QGROUP)      // 8

#define PITCH 336              // smem row pitch bytes (21*16)
#define ABYTES (QGROUP * PITCH)        // 21504
#define BBYTES (BN * PITCH)            // 21504
#define DPITCH 65              // floats (odd -> conflict-free row scan)
#define DBYTES (QGROUP * DPITCH * 4)   // 16640
#define SVBYTES (BN * 4)
#define SMEM_BYTES (1024 + ABYTES + 2 * BBYTES + DBYTES + SVBYTES)   // ~82.4 KB

// ---------------- device scratch (no allocation allowed) -------------------
__device__ float g_invnorm[VOCAB];
__device__ float g_scale[VOCAB];                       // maxabs*inv/127
__device__ __align__(128) signed char g_E8[(size_t)VOCAB * KP];   // 128 MB
__device__ __align__(128) signed char g_Q8[NQ * KP];
__device__ float g_cv[(size_t)NQ * GRIDX * CAND];
__device__ int   g_ci[(size_t)NQ * GRIDX * CAND];

// ---------------- PTX helpers ----------------------------------------------
__device__ __forceinline__ uint32_t smem_u32(const void* p) {
    uint32_t a;
    asm("{ .reg .u64 t; cvta.to.shared.u64 t, %1; cvt.u32.u64 %0, t; }" : "=r"(a) : "l"(p));
    return a;
}
__device__ __forceinline__ void cpa16(uint32_t dst, const void* src) {
    asm volatile("cp.async.cg.shared.global [%0], [%1], 16;" :: "r"(dst), "l"(src) : "memory");
}
#define CP_COMMIT() asm volatile("cp.async.commit_group;" ::: "memory")
#define CP_WAIT(n)  asm volatile("cp.async.wait_group %0;" :: "n"(n) : "memory")

__device__ __forceinline__ int4 lds128(uint32_t addr) {
    int4 v;
    asm volatile("ld.shared.v4.b32 {%0,%1,%2,%3}, [%4];"
                 : "=r"(v.x), "=r"(v.y), "=r"(v.z), "=r"(v.w) : "r"(addr));
    return v;
}

// ---------------- ordering helpers -----------------------------------------
__device__ __forceinline__ bool better(float av, int an, float bv, int bn) {
    return (av > bv) || (av == bv && an < bn);
}
__device__ __forceinline__ void ins16(float s, int n, float* v, int* nn) {
    if (better(s, n, v[CAND - 1], nn[CAND - 1])) {
        v[CAND - 1] = s; nn[CAND - 1] = n;
        #pragma unroll
        for (int j = CAND - 1; j > 0; j--) {
            if (better(v[j], nn[j], v[j - 1], nn[j - 1])) {
                float tv = v[j]; v[j] = v[j - 1]; v[j - 1] = tv;
                int tn = nn[j]; nn[j] = nn[j - 1]; nn[j - 1] = tn;
            }
        }
    }
}
__device__ __forceinline__ void merge16(float* v, int* nn, const float* ov, const int* on) {
    float rv[CAND]; int rn[CAND]; int a = 0, b = 0;
    #pragma unroll
    for (int j = 0; j < CAND; j++) {
        bool ta = better(v[a], nn[a], ov[b], on[b]);
        rv[j] = ta ? v[a] : ov[b];
        rn[j] = ta ? nn[a] : on[b];
        if (ta) a++; else b++;
    }
    #pragma unroll
    for (int j = 0; j < CAND; j++) { v[j] = rv[j]; nn[j] = rn[j]; }
}

// ---------------------------------------------------------------------------
// Kernel 1: per-row invnorm + maxabs -> int8 quantized table + scale
// ---------------------------------------------------------------------------
__global__ void prep_kernel(const float* __restrict__ E) {
    int row = blockIdx.x * (blockDim.x >> 5) + (threadIdx.x >> 5);
    int lane = threadIdx.x & 31;
    if (row >= VOCAB) return;
    const float4* r4 = (const float4*)(E + (size_t)row * DIM);
    float s = 0.f, mx = 0.f;
    for (int i = lane; i < DIM / 4; i += 32) {
        float4 v = r4[i];
        s += v.x * v.x + v.y * v.y + v.z * v.z + v.w * v.w;
        mx = fmaxf(mx, fmaxf(fmaxf(fabsf(v.x), fabsf(v.y)), fmaxf(fabsf(v.z), fabsf(v.w))));
    }
    #pragma unroll
    for (int off = 16; off; off >>= 1) {
        s += __shfl_xor_sync(0xffffffffu, s, off);
        mx = fmaxf(mx, __shfl_xor_sync(0xffffffffu, mx, off));
    }
    float inv = 1.0f / sqrtf(s);
    float qs = 127.0f / mx;
    if (lane == 0) { g_invnorm[row] = inv; g_scale[row] = mx * inv * (1.0f / 127.0f); }
    const float* src = E + (size_t)row * DIM;
    int* dst = (int*)(g_E8 + (size_t)row * KP);
    for (int j = lane; j < KP / 4; j += 32) {
        int k = 4 * j;
        int b0 = (k     < DIM) ? __float2int_rn(src[k]     * qs) : 0;
        int b1 = (k + 1 < DIM) ? __float2int_rn(src[k + 1] * qs) : 0;
        int b2 = (k + 2 < DIM) ? __float2int_rn(src[k + 2] * qs) : 0;
        int b3 = (k + 3 < DIM) ? __float2int_rn(src[k + 3] * qs) : 0;
        dst[j] = (b0 & 0xff) | ((b1 & 0xff) << 8) | ((b2 & 0xff) << 16) | ((b3 & 0xff) << 24);
    }
}

// ---------------------------------------------------------------------------
// Kernel 2: gather queries -> int8 (query-side scale uniform per query)
// ---------------------------------------------------------------------------
__global__ void gatherq_kernel(const float* __restrict__ E, const int* __restrict__ ids) {
    int q = blockIdx.x * (blockDim.x >> 5) + (threadIdx.x >> 5);
    int lane = threadIdx.x & 31;
    if (q >= NQ) return;
    int id = ids[q];
    const float* src = E + (size_t)id * DIM;
    float mx = 0.f;
    for (int k = lane; k < DIM; k += 32) mx = fmaxf(mx, fabsf(src[k]));
    #pragma unroll
    for (int off = 16; off; off >>= 1) mx = fmaxf(mx, __shfl_xor_sync(0xffffffffu, mx, off));
    float qs = 127.0f / mx;
    int* dst = (int*)(g_Q8 + (size_t)q * KP);
    for (int j = lane; j < KP / 4; j += 32) {
        int k = 4 * j;
        int b0 = (k     < DIM) ? __float2int_rn(src[k]     * qs) : 0;
        int b1 = (k + 1 < DIM) ? __float2int_rn(src[k + 1] * qs) : 0;
        int b2 = (k + 2 < DIM) ? __float2int_rn(src[k + 2] * qs) : 0;
        int b3 = (k + 3 < DIM) ? __float2int_rn(src[k + 3] * qs) : 0;
        dst[j] = (b0 & 0xff) | ((b1 & 0xff) << 8) | ((b2 & 0xff) << 16) | ((b3 & 0xff) << 24);
    }
}

// ---------------------------------------------------------------------------
// Kernel 3: dp4a GEMM (64 queries x 64 vocab x K=320) + per-query top-16
// 256 threads: tx = tid&15 (cols tx+16j, j<4), ty = tid>>4 (rows ty+16i, i<4)
// 2 CTAs/SM for latency hiding.
// ---------------------------------------------------------------------------
__global__ __launch_bounds__(256, 2) void gemm_topk_kernel() {
    extern __shared__ char smem[];
    uint32_t sb = smem_u32(smem);
    uint32_t ab = (sb + 1023u) & ~1023u;
    const uint32_t A_S = ab;
    const uint32_t B_S = ab + ABYTES;
    float* Ds  = (float*)(smem + (ab - sb) + ABYTES + 2 * BBYTES);
    float* svs = (float*)(smem + (ab - sb) + ABYTES + 2 * BBYTES + DBYTES);

    const int tid = threadIdx.x;
    const int tx = tid & 15;
    const int ty = tid >> 4;
    const int qg = blockIdx.x;
    const int bx = blockIdx.y;
    const int nt = (NTILES - bx + GRIDX - 1) / GRIDX;

    // A load (resident, 64 rows) + first B tile
    const signed char* Qsrc = g_Q8 + (size_t)qg * QGROUP * KP;
    for (int i = tid; i < QGROUP * NCH; i += 256)
        cpa16(A_S + (i / NCH) * PITCH + (i % NCH) * 16, Qsrc + (size_t)(i / NCH) * KP + (i % NCH) * 16);
    {
        const signed char* src = g_E8 + (size_t)bx * BN * KP;
        for (int i = tid; i < BN * NCH; i += 256)
            cpa16(B_S + (i / NCH) * PITCH + (i % NCH) * 16, src + (size_t)(i / NCH) * KP + (i % NCH) * 16);
    }
    CP_COMMIT();

    float cv[CAND]; int ci[CAND];
    #pragma unroll
    for (int j = 0; j < CAND; j++) { cv[j] = -1e30f; ci[j] = 0x7fffffff; }

    for (int t = 0; t < nt; t++) {
        if (t + 1 < nt) {
            int vt = bx + (t + 1) * GRIDX;
            uint32_t base = B_S + (uint32_t)((t + 1) & 1) * BBYTES;
            const signed char* src = g_E8 + (size_t)vt * BN * KP;
            for (int i = tid; i < BN * NCH; i += 256)
                cpa16(base + (i / NCH) * PITCH + (i % NCH) * 16, src + (size_t)(i / NCH) * KP + (i % NCH) * 16);
            CP_COMMIT();
            CP_WAIT(1);
        } else {
            CP_WAIT(0);
        }
        if (tid < BN) svs[tid] = g_scale[(bx + t * GRIDX) * BN + tid];
        __syncthreads();

        const uint32_t Bb = B_S + (uint32_t)(t & 1) * BBYTES;
        int acc[4][4];
        #pragma unroll
        for (int i = 0; i < 4; i++)
            #pragma unroll
            for (int j = 0; j < 4; j++) acc[i][j] = 0;

        #pragma unroll 4
        for (int c = 0; c < NCH; c++) {
            int4 bf[4];
            #pragma unroll
            for (int j = 0; j < 4; j++)
                bf[j] = lds128(Bb + (uint32_t)(tx + 16 * j) * PITCH + c * 16);
            #pragma unroll
            for (int i = 0; i < 4; i++) {
                int4 af = lds128(A_S + (uint32_t)(ty + 16 * i) * PITCH + c * 16);
                #pragma unroll
                for (int j = 0; j < 4; j++) {
                    int s = acc[i][j];
                    s = __dp4a(af.x, bf[j].x, s);
                    s = __dp4a(af.y, bf[j].y, s);
                    s = __dp4a(af.z, bf[j].z, s);
                    s = __dp4a(af.w, bf[j].w, s);
                    acc[i][j] = s;
                }
            }
        }

        // stage scaled D to smem
        #pragma unroll
        for (int i = 0; i < 4; i++) {
            int r = ty + 16 * i;
            #pragma unroll
            for (int j = 0; j < 4; j++) {
                int cidx = tx + 16 * j;
                Ds[r * DPITCH + cidx] = (float)acc[i][j] * svs[cidx];
            }
        }
        __syncthreads();

        // per-query top-16 scan (1 thread per query row)
        if (tid < QGROUP) {
            const float* row = Ds + tid * DPITCH;
            int vbase = (bx + t * GRIDX) * BN;
            #pragma unroll 8
            for (int cc = 0; cc < BN; cc++) ins16(row[cc], vbase + cc, cv, ci);
        }
        __syncthreads();
    }

    if (tid < QGROUP) {
        int q = qg * QGROUP + tid;
        size_t base = ((size_t)q * GRIDX + bx) * CAND;
        #pragma unroll
        for (int j = 0; j < CAND; j++) { g_cv[base + j] = cv[j]; g_ci[base + j] = ci[j]; }
    }
}

// ---------------------------------------------------------------------------
// Kernel 4: global approx top-16 -> exact fp32 rescore -> top-5 out
// ---------------------------------------------------------------------------
__global__ void final_kernel(const float* __restrict__ E, const int* __restrict__ ids,
                             float* __restrict__ out) {
    __shared__ float sv[256][CAND];
    __shared__ int   sn[256][CAND];
    __shared__ float ev[CAND];
    int q = blockIdx.x, tid = threadIdx.x;

    float v[CAND]; int nn[CAND];
    #pragma unroll
    for (int j = 0; j < CAND; j++) { v[j] = -1e30f; nn[j] = 0x7fffffff; }
    size_t base = (size_t)q * GRIDX * CAND;
    for (int i = tid; i < GRIDX * CAND; i += 256) ins16(g_cv[base + i], g_ci[base + i], v, nn);
    #pragma unroll
    for (int j = 0; j < CAND; j++) { sv[tid][j] = v[j]; sn[tid][j] = nn[j]; }
    __syncthreads();
    for (int s = 128; s > 0; s >>= 1) {
        if (tid < s) {
            float ov[CAND]; int on[CAND];
            #pragma unroll
            for (int j = 0; j < CAND; j++) {
                v[j] = sv[tid][j]; nn[j] = sn[tid][j];
                ov[j] = sv[tid + s][j]; on[j] = sn[tid + s][j];
            }
            merge16(v, nn, ov, on);
            #pragma unroll
            for (int j = 0; j < CAND; j++) { sv[tid][j] = v[j]; sn[tid][j] = nn[j]; }
        }
        __syncthreads();
    }
    // exact fp32 rescore of the 16 surviving candidates
    int wid = tid >> 5, lane = tid & 31;
    int qid = ids[q];
    float invq = g_invnorm[qid];
    for (int c = wid; c < CAND; c += 8) {
        int vi = sn[0][c];
        float val = -1e30f;
        if (vi >= 0 && vi < VOCAB) {
            const float* a = E + (size_t)qid * DIM;
            const float* b = E + (size_t)vi * DIM;
            float s = 0.f;
            for (int k = lane; k < DIM; k += 32) s += a[k] * b[k];
            #pragma unroll
            for (int off = 16; off; off >>= 1) s += __shfl_xor_sync(0xffffffffu, s, off);
            val = s * invq * g_invnorm[vi];
        }
        if (lane == 0) ev[c] = val;
    }
    __syncthreads();
    if (tid == 0) {
        bool used[CAND];
        #pragma unroll
        for (int j = 0; j < CAND; j++) used[j] = false;
        for (int j = 0; j < TOPK; j++) {
            int best = -1;
            for (int c = 0; c < CAND; c++) {
                if (used[c]) continue;
                if (best < 0 || better(ev[c], sn[0][c], ev[best], sn[0][best])) best = c;
            }
            used[best] = true;
            out[q * TOPK + j] = ev[best];
            out[NQ * TOPK + q * TOPK + j] = (float)sn[0][best];
        }
    }
}

// ---------------------------------------------------------------------------
extern "C" void kernel_launch(void* const* d_in, const int* in_sizes, int n_in,
                              void* d_out, int out_size) {
    const float* E = (const float*)d_in[0];
    const int* ids = (const int*)d_in[1];
    float* out = (float*)d_out;

    cudaFuncSetAttribute(gemm_topk_kernel, cudaFuncAttributeMaxDynamicSharedMemorySize, SMEM_BYTES);

    prep_kernel<<<VOCAB / 8, 256>>>(E);
    gatherq_kernel<<<NQ / 8, 256>>>(E, ids);
    gemm_topk_kernel<<<dim3(NQG, GRIDX), 256, SMEM_BYTES>>>();
    final_kernel<<<NQ, 256>>>(E, ids, out);
}